// round 15
// baseline (speedup 1.0000x reference)
#include <cuda_runtime.h>
#include <cuda_bf16.h>

using u64 = unsigned long long;

__device__ __forceinline__ void fma2(u64& d, u64 a, u64 b) {
    asm("fma.rn.f32x2 %0, %1, %2, %0;" : "+l"(d) : "l"(a), "l"(b));
}
__device__ __forceinline__ u64 pack2(float x, float y) {
    u64 d;
    asm("mov.b64 %0, {%1, %2};" : "=l"(d) : "f"(x), "f"(y));
    return d;
}
__device__ __forceinline__ void unpack2(u64 v, float& x, float& y) {
    asm("mov.b64 {%0, %1}, %2;" : "=f"(x), "=f"(y) : "l"(v));
}
__device__ __forceinline__ void cp_async16(void* smem, const void* gmem) {
    unsigned s = (unsigned)__cvta_generic_to_shared(smem);
    asm volatile("cp.async.cg.shared.global [%0], [%1], 16;" :: "r"(s), "l"(gmem));
}
__device__ __forceinline__ void cp_commit() {
    asm volatile("cp.async.commit_group;");
}
template <int N>
__device__ __forceinline__ void cp_wait() {
    asm volatile("cp.async.wait_group %0;" :: "n"(N));
}
// 1D bulk store smem -> gmem on the async (TMA) proxy.
__device__ __forceinline__ void bulk_store(void* gdst, const void* ssrc, int bytes) {
    unsigned s = (unsigned)__cvta_generic_to_shared(ssrc);
    asm volatile("cp.async.bulk.global.shared::cta.bulk_group [%0], [%1], %2;"
                 :: "l"(gdst), "r"(s), "r"(bytes) : "memory");
}
__device__ __forceinline__ void bulk_commit() {
    asm volatile("cp.async.bulk.commit_group;" ::: "memory");
}
__device__ __forceinline__ void bulk_wait_read0() {   // smem source reusable
    asm volatile("cp.async.bulk.wait_group.read 0;" ::: "memory");
}
__device__ __forceinline__ void bulk_wait_all0() {    // full completion
    asm volatile("cp.async.bulk.wait_group 0;" ::: "memory");
}
__device__ __forceinline__ void fence_async_shared() {
    asm volatile("fence.proxy.async.shared::cta;" ::: "memory");
}

constexpr int CTA   = 128;  // 4 warps; occupancy 7 -> 72-reg budget
constexpr int TILE  = 128;  // rows per tile (== blockDim.x); warp owns 32 rows
constexpr int WARPS = 4;

// Core per-row computation (proven version).
// sPtI[j][2i+m] = -P_m[i][j]  (NEGATED + interleaved, 24-float rows).
// acc[i] starts at (1,1), so post-matmul acc[i] = (u_i, v_i) = (1-l1_i, 1-l2_i).
// y_k = 1 - prod_{i+j=k} max(u_i, v_j), normalized.
__device__ __forceinline__ void compute_row(const float2 av[5], const float2 bv[5],
                                            const float (*sPtI)[24],
                                            float res[19]) {
    u64 acc[10];
    const u64 ONE2 = pack2(1.0f, 1.0f);
#pragma unroll
    for (int i = 0; i < 10; ++i) acc[i] = ONE2;

#pragma unroll
    for (int jj = 0; jj < 5; ++jj) {
#pragma unroll
        for (int h = 0; h < 2; ++h) {
            int j = jj * 2 + h;
            float a = h ? av[jj].y : av[jj].x;
            float b = h ? bv[jj].y : bv[jj].x;
            u64 ab = pack2(a, b);                       // (p1_j, p2_j)
            const ulonglong2* r = (const ulonglong2*)&sPtI[j][0];
            ulonglong2 q0 = r[0], q1 = r[1], q2 = r[2], q3 = r[3], q4 = r[4];
            fma2(acc[0], ab, q0.x);
            fma2(acc[1], ab, q0.y);
            fma2(acc[2], ab, q1.x);
            fma2(acc[3], ab, q1.y);
            fma2(acc[4], ab, q2.x);
            fma2(acc[5], ab, q2.y);
            fma2(acc[6], ab, q3.x);
            fma2(acc[7], ab, q3.y);
            fma2(acc[8], ab, q4.x);
            fma2(acc[9], ab, q4.y);
        }
    }

    float u[10], v[10];
#pragma unroll
    for (int i = 0; i < 10; ++i) unpack2(acc[i], u[i], v[i]);

    float prod[19];
#pragma unroll
    for (int j = 0; j < 10; ++j) prod[j] = fmaxf(u[0], v[j]);     // i = 0 row
#pragma unroll
    for (int i = 1; i < 10; ++i) prod[9 + i] = fmaxf(u[i], v[9]); // j = 9 col
#pragma unroll
    for (int i = 1; i < 10; ++i) {
#pragma unroll
        for (int j = 0; j < 9; ++j)
            prod[i + j] *= fmaxf(u[i], v[j]);
    }

    float s0 = 0.f, s1 = 0.f, s2 = 0.f, s3 = 0.f;
#pragma unroll
    for (int k = 0; k < 19; ++k) {
        res[k] = 1.0f - prod[k];
        if ((k & 3) == 0) s0 += res[k];
        else if ((k & 3) == 1) s1 += res[k];
        else if ((k & 3) == 2) s2 += res[k];
        else s3 += res[k];
    }
    float sum = (s0 + s1) + (s2 + s3);
    float inv = __fdividef(1.0f, sum + 1e-9f);
#pragma unroll
    for (int k = 0; k < 19; ++k) res[k] *= inv;
}

__global__ __launch_bounds__(CTA, 7)
void bacon_kernel(const float* __restrict__ p1,
                  const float* __restrict__ p2,
                  const float* __restrict__ W1,
                  const float* __restrict__ W2,
                  float* __restrict__ out,
                  int B, int ntiles) {
    // per-warp private double-buffered staging slices (2 x 640 floats):
    // buffer = p1 rows [0,320) + p2 rows [320,640); reused for output staging
    // (32*19 = 608 floats), drained to gmem by a TMA 1D bulk store.
    __shared__ __align__(16) float ws[WARPS][2][640];
    __shared__ __align__(16) float sPtI[10][24];   // interleaved NEGATED: [j][2i+m]

    const int tid  = threadIdx.x;
    const int lane = tid & 31;
    const int w    = tid >> 5;
    const int G    = gridDim.x;

    // Inline soft-perm prep: threads 0..19 (thread = matrix m, row r).
    if (tid < 20) {
        const float* W = (tid < 10) ? W1 : W2;
        int r = tid % 10, m = tid / 10;
        float row[10];
        float lo = 1e30f, hi = -1e30f;
#pragma unroll
        for (int j = 0; j < 10; ++j) {
            row[j] = W[r * 10 + j];
            lo = fminf(lo, row[j]);
            hi = fmaxf(hi, row[j]);
        }
        float invr = 1.0f / (hi - lo + 1e-8f);
        float s = 0.0f;
#pragma unroll
        for (int j = 0; j < 10; ++j) {
            row[j] = (row[j] - lo) * invr;
            s += row[j];
        }
        float invs = 1.0f / (s + 1e-8f);
#pragma unroll
        for (int j = 0; j < 10; ++j)
            sPtI[j][2 * r + m] = -(row[j] * invs);   // NEGATED interleaved store
    }
    __syncthreads();   // the only block barrier

    // stage this warp's 32-row slab of tile t into buffer buf (fast path only).
    // Branch-free except i=2 (the p1/p2 boundary). TILE=128 rows -> 320 float4
    // per input array per tile; this warp covers float4 [w*80, (w+1)*80).
    auto stage = [&](int buf, int t) {
        const float4* g1 = (const float4*)p1 + (size_t)t * 320 + w * 80;
        const float4* g2 = (const float4*)p2 + (size_t)t * 320 + w * 80;
        float4* s = (float4*)ws[w][buf];
        cp_async16(&s[lane],       g1 + lane);              // i=0: [0,32)
        cp_async16(&s[lane + 32],  g1 + lane + 32);         // i=1: [32,64)
        {                                                   // i=2: [64,96) straddles 80
            int idx = lane + 64;
            const float4* src = (idx < 80) ? (g1 + idx) : (g2 + (idx - 80));
            cp_async16(&s[idx], src);
        }
        cp_async16(&s[lane + 96],  g2 + lane + 16);         // i=3: [96,128)
        cp_async16(&s[lane + 128], g2 + lane + 48);         // i=4: [128,160)
    };

    int cur = blockIdx.x;
    if (cur >= ntiles) return;
    const bool cur_full0 = (cur * TILE + (w + 1) * 32 <= B);
    if (cur_full0) { stage(0, cur); cp_commit(); }

    int p = 0;
    for (; cur < ntiles; cur += G) {
        const int nxt = cur + G;
        const bool cur_full = (cur * TILE + (w + 1) * 32 <= B);
        const bool nxt_full = (nxt < ntiles) && (nxt * TILE + (w + 1) * 32 <= B);

        if (nxt_full) {
            // buffer (1-p) was bulk-stored last iteration; ensure the TMA read
            // of its smem is done before overwriting. (No-op first time.)
            if (lane == 0) bulk_wait_read0();
            __syncwarp();
            stage(1 - p, nxt);
            cp_commit();
        }

        if (cur_full) {
            if (nxt_full) cp_wait<1>(); else cp_wait<0>();
            __syncwarp();

            float* slice = ws[w][p];
            float2 av[5], bv[5];
#pragma unroll
            for (int jj = 0; jj < 5; ++jj) {
                av[jj] = *(const float2*)&slice[lane * 10 + jj * 2];
                bv[jj] = *(const float2*)&slice[320 + lane * 10 + jj * 2];
            }
            __syncwarp();   // input reads done before output staging overwrites

            float res[19];
            compute_row(av, bv, sPtI, res);

            // stage final row-major output (stride 19: conflict-free STS)
#pragma unroll
            for (int k = 0; k < 19; ++k) slice[lane * 19 + k] = res[k];
            fence_async_shared();   // order generic STS before async-proxy read
            __syncwarp();

            if (lane == 0) {
                // one bulk store drains the whole 32x19 slab (2432 B)
                float* gdst = out + (size_t)cur * (TILE * 19) + w * 608;
                bulk_store(gdst, slice, 2432);
                bulk_commit();
            }
            // buffer p protected by bulk_wait_read0 before its next restage.
        } else {
            // tail slab: scalar, no smem
            cp_wait<0>();
            int row = cur * TILE + w * 32 + lane;
            if (row < B) {
                float2 av[5], bv[5];
#pragma unroll
                for (int jj = 0; jj < 5; ++jj) {
                    av[jj] = *(const float2*)&p1[(size_t)row * 10 + jj * 2];
                    bv[jj] = *(const float2*)&p2[(size_t)row * 10 + jj * 2];
                }
                float res[19];
                compute_row(av, bv, sPtI, res);
#pragma unroll
                for (int k = 0; k < 19; ++k)
                    out[(size_t)row * 19 + k] = res[k];
            }
            __syncwarp();
        }
        p ^= 1;
    }

    // drain outstanding bulk stores before kernel exit
    bulk_wait_all0();
}

extern "C" void kernel_launch(void* const* d_in, const int* in_sizes, int n_in,
                              void* d_out, int out_size) {
    const float* p1 = (const float*)d_in[0];
    const float* p2 = (const float*)d_in[1];
    const float* W1 = (const float*)d_in[2];
    const float* W2 = (const float*)d_in[3];
    float* out = (float*)d_out;

    int B = in_sizes[0] / 10;
    int ntiles = (B + TILE - 1) / TILE;   // B=262144 -> 2048 tiles

    // one wave at occupancy 7 (128-thread CTAs) on 148 SMs
    int G = 148 * 7;
    if (G > ntiles) G = ntiles;
    if (G < 1) G = 1;

    bacon_kernel<<<G, CTA>>>(p1, p2, W1, W2, out, B, ntiles);
}

// round 16
// speedup vs baseline: 1.0201x; 1.0201x over previous
#include <cuda_runtime.h>
#include <cuda_bf16.h>

using u64 = unsigned long long;

__device__ __forceinline__ void fma2(u64& d, u64 a, u64 b) {
    asm("fma.rn.f32x2 %0, %1, %2, %0;" : "+l"(d) : "l"(a), "l"(b));
}
__device__ __forceinline__ u64 pack2(float x, float y) {
    u64 d;
    asm("mov.b64 %0, {%1, %2};" : "=l"(d) : "f"(x), "f"(y));
    return d;
}
__device__ __forceinline__ void unpack2(u64 v, float& x, float& y) {
    asm("mov.b64 {%0, %1}, %2;" : "=f"(x), "=f"(y) : "l"(v));
}
__device__ __forceinline__ void cp_async16(void* smem, const void* gmem) {
    unsigned s = (unsigned)__cvta_generic_to_shared(smem);
    asm volatile("cp.async.cg.shared.global [%0], [%1], 16;" :: "r"(s), "l"(gmem));
}
__device__ __forceinline__ void cp_commit() {
    asm volatile("cp.async.commit_group;");
}
template <int N>
__device__ __forceinline__ void cp_wait() {
    asm volatile("cp.async.wait_group %0;" :: "n"(N));
}
// 1D bulk store smem -> gmem on the async (TMA) proxy.
__device__ __forceinline__ void bulk_store(void* gdst, const void* ssrc, int bytes) {
    unsigned s = (unsigned)__cvta_generic_to_shared(ssrc);
    asm volatile("cp.async.bulk.global.shared::cta.bulk_group [%0], [%1], %2;"
                 :: "l"(gdst), "r"(s), "r"(bytes) : "memory");
}
__device__ __forceinline__ void bulk_commit() {
    asm volatile("cp.async.bulk.commit_group;" ::: "memory");
}
__device__ __forceinline__ void bulk_wait_read0() {   // smem source reusable
    asm volatile("cp.async.bulk.wait_group.read 0;" ::: "memory");
}
__device__ __forceinline__ void bulk_wait_all0() {    // full completion
    asm volatile("cp.async.bulk.wait_group 0;" ::: "memory");
}
__device__ __forceinline__ void fence_async_shared() {
    asm volatile("fence.proxy.async.shared::cta;" ::: "memory");
}

constexpr int CTA   = 128;  // 4 warps; occupancy 5 -> 102-reg budget (clean fit)
constexpr int TILE  = 256;  // rows per tile; warp owns 64 rows, 2 per thread
constexpr int WARPS = 4;

// Finish phase for one row (proven epilogue).
__device__ __forceinline__ void finish_row(const u64 acc[10], float res[19]) {
    float u[10], v[10];
#pragma unroll
    for (int i = 0; i < 10; ++i) unpack2(acc[i], u[i], v[i]);

    float prod[19];
#pragma unroll
    for (int j = 0; j < 10; ++j) prod[j] = fmaxf(u[0], v[j]);     // i = 0 row
#pragma unroll
    for (int i = 1; i < 10; ++i) prod[9 + i] = fmaxf(u[i], v[9]); // j = 9 col
#pragma unroll
    for (int i = 1; i < 10; ++i) {
#pragma unroll
        for (int j = 0; j < 9; ++j)
            prod[i + j] *= fmaxf(u[i], v[j]);
    }

    float s0 = 0.f, s1 = 0.f, s2 = 0.f, s3 = 0.f;
#pragma unroll
    for (int k = 0; k < 19; ++k) {
        res[k] = 1.0f - prod[k];
        if ((k & 3) == 0) s0 += res[k];
        else if ((k & 3) == 1) s1 += res[k];
        else if ((k & 3) == 2) s2 += res[k];
        else s3 += res[k];
    }
    float sum = (s0 + s1) + (s2 + s3);
    float inv = __fdividef(1.0f, sum + 1e-9f);
#pragma unroll
    for (int k = 0; k < 19; ++k) res[k] *= inv;
}

// Two rows per thread: every P column loaded ONCE per pair (25 LDS.128/row),
// feeding two independent FFMA2 streams. Inputs streamed per-jj from smem
// (8-reg transient) to bound register pressure. sPtI[j][2i+m] = -P_m[i][j];
// acc init (1,1) -> acc[i] = (u_i, v_i) post-matmul. (Numerics verified R11.)
__device__ __forceinline__ void compute_rows2(
    const float* __restrict__ A0, const float* __restrict__ A1,
    const float* __restrict__ B0, const float* __restrict__ B1,
    const float (*sPtI)[24], float res[2][19])
{
    u64 acc0[10], acc1[10];
    const u64 ONE2 = pack2(1.0f, 1.0f);
#pragma unroll
    for (int i = 0; i < 10; ++i) { acc0[i] = ONE2; acc1[i] = ONE2; }

#pragma unroll
    for (int jj = 0; jj < 5; ++jj) {
        float2 a0 = *(const float2*)(A0 + 2 * jj);
        float2 a1 = *(const float2*)(A1 + 2 * jj);
        float2 b0 = *(const float2*)(B0 + 2 * jj);
        float2 b1 = *(const float2*)(B1 + 2 * jj);
#pragma unroll
        for (int h = 0; h < 2; ++h) {
            int j = 2 * jj + h;
            u64 ab0 = pack2(h ? a0.y : a0.x, h ? b0.y : b0.x);
            u64 ab1 = pack2(h ? a1.y : a1.x, h ? b1.y : b1.x);
            const ulonglong2* r = (const ulonglong2*)&sPtI[j][0];
            ulonglong2 q0 = r[0], q1 = r[1], q2 = r[2], q3 = r[3], q4 = r[4];
            fma2(acc0[0], ab0, q0.x);  fma2(acc1[0], ab1, q0.x);
            fma2(acc0[1], ab0, q0.y);  fma2(acc1[1], ab1, q0.y);
            fma2(acc0[2], ab0, q1.x);  fma2(acc1[2], ab1, q1.x);
            fma2(acc0[3], ab0, q1.y);  fma2(acc1[3], ab1, q1.y);
            fma2(acc0[4], ab0, q2.x);  fma2(acc1[4], ab1, q2.x);
            fma2(acc0[5], ab0, q2.y);  fma2(acc1[5], ab1, q2.y);
            fma2(acc0[6], ab0, q3.x);  fma2(acc1[6], ab1, q3.x);
            fma2(acc0[7], ab0, q3.y);  fma2(acc1[7], ab1, q3.y);
            fma2(acc0[8], ab0, q4.x);  fma2(acc1[8], ab1, q4.x);
            fma2(acc0[9], ab0, q4.y);  fma2(acc1[9], ab1, q4.y);
        }
    }

    finish_row(acc0, res[0]);
    finish_row(acc1, res[1]);
}

__global__ __launch_bounds__(CTA, 5)
void bacon_kernel(const float* __restrict__ p1,
                  const float* __restrict__ p2,
                  const float* __restrict__ W1,
                  const float* __restrict__ W2,
                  float* __restrict__ out,
                  int B, int ntiles) {
    // per-warp private double-buffered slabs (2 x 1280 floats): 64 rows each,
    // p1 [0,640) + p2 [640,1280); reused for output staging (64*19 = 1216),
    // drained by one TMA 1D bulk store per slab.
    __shared__ __align__(16) float ws[WARPS][2][1280];
    __shared__ __align__(16) float sPtI[10][24];   // interleaved NEGATED: [j][2i+m]

    const int tid  = threadIdx.x;
    const int lane = tid & 31;
    const int w    = tid >> 5;
    const int G    = gridDim.x;

    // Inline soft-perm prep: threads 0..19 (thread = matrix m, row r).
    if (tid < 20) {
        const float* W = (tid < 10) ? W1 : W2;
        int r = tid % 10, m = tid / 10;
        float row[10];
        float lo = 1e30f, hi = -1e30f;
#pragma unroll
        for (int j = 0; j < 10; ++j) {
            row[j] = W[r * 10 + j];
            lo = fminf(lo, row[j]);
            hi = fmaxf(hi, row[j]);
        }
        float invr = 1.0f / (hi - lo + 1e-8f);
        float s = 0.0f;
#pragma unroll
        for (int j = 0; j < 10; ++j) {
            row[j] = (row[j] - lo) * invr;
            s += row[j];
        }
        float invs = 1.0f / (s + 1e-8f);
#pragma unroll
        for (int j = 0; j < 10; ++j)
            sPtI[j][2 * r + m] = -(row[j] * invs);   // NEGATED interleaved store
    }
    __syncthreads();   // the only block barrier

    // stage this warp's 64-row slab of tile t into buffer buf (fast path only).
    // 160 float4 per array per slab = exactly 5 unpredicated cp.async/lane each.
    auto stage = [&](int buf, int t) {
        const float4* g1 = (const float4*)p1 + (size_t)t * 640 + w * 160;
        const float4* g2 = (const float4*)p2 + (size_t)t * 640 + w * 160;
        float4* s = (float4*)ws[w][buf];
#pragma unroll
        for (int i = 0; i < 5; ++i) {
            cp_async16(&s[lane + i * 32],       g1 + lane + i * 32);
            cp_async16(&s[160 + lane + i * 32], g2 + lane + i * 32);
        }
    };

    int cur = blockIdx.x;
    if (cur >= ntiles) return;
    const bool cur_full0 = (cur * TILE + (w + 1) * 64 <= B);
    if (cur_full0) { stage(0, cur); cp_commit(); }

    int p = 0;
    for (; cur < ntiles; cur += G) {
        const int nxt = cur + G;
        const bool cur_full = (cur * TILE + (w + 1) * 64 <= B);
        const bool nxt_full = (nxt < ntiles) && (nxt * TILE + (w + 1) * 64 <= B);

        if (nxt_full) {
            // buffer (1-p) was bulk-stored last iteration; ensure the TMA read
            // of its smem is done before overwriting. (No-op first time.)
            if (lane == 0) bulk_wait_read0();
            __syncwarp();
            stage(1 - p, nxt);
            cp_commit();
        }

        if (cur_full) {
            if (nxt_full) cp_wait<1>(); else cp_wait<0>();
            __syncwarp();

            float* slice = ws[w][p];
            float res[2][19];
            compute_rows2(slice + lane * 10,       slice + (lane + 32) * 10,
                          slice + 640 + lane * 10, slice + 640 + (lane + 32) * 10,
                          sPtI, res);
            __syncwarp();   // all lanes' input reads done before output staging

            // stage final row-major output (stride 19: conflict-free STS)
#pragma unroll
            for (int k = 0; k < 19; ++k) {
                slice[lane * 19 + k]        = res[0][k];
                slice[(lane + 32) * 19 + k] = res[1][k];
            }
            fence_async_shared();   // order generic STS before async-proxy read
            __syncwarp();

            if (lane == 0) {
                // one bulk store drains the whole 64x19 slab (4864 B)
                float* gdst = out + (size_t)cur * (TILE * 19) + w * 1216;
                bulk_store(gdst, slice, 4864);
                bulk_commit();
            }
            // buffer p protected by bulk_wait_read0 before its next restage.
        } else {
            // tail slab: scalar per-row, no smem
            cp_wait<0>();
            int r0 = cur * TILE + w * 64 + lane;
            int r1 = r0 + 32;
#pragma unroll
            for (int rr = 0; rr < 2; ++rr) {
                int row = rr ? r1 : r0;
                if (row < B) {
                    float ax[10], bx[10];
#pragma unroll
                    for (int j = 0; j < 10; ++j) {
                        ax[j] = p1[(size_t)row * 10 + j];
                        bx[j] = p2[(size_t)row * 10 + j];
                    }
                    u64 acc[10];
                    const u64 ONE2 = pack2(1.0f, 1.0f);
#pragma unroll
                    for (int i = 0; i < 10; ++i) acc[i] = ONE2;
#pragma unroll
                    for (int j = 0; j < 10; ++j) {
                        u64 ab = pack2(ax[j], bx[j]);
                        const ulonglong2* r = (const ulonglong2*)&sPtI[j][0];
                        ulonglong2 q0 = r[0], q1 = r[1], q2 = r[2], q3 = r[3], q4 = r[4];
                        fma2(acc[0], ab, q0.x);
                        fma2(acc[1], ab, q0.y);
                        fma2(acc[2], ab, q1.x);
                        fma2(acc[3], ab, q1.y);
                        fma2(acc[4], ab, q2.x);
                        fma2(acc[5], ab, q2.y);
                        fma2(acc[6], ab, q3.x);
                        fma2(acc[7], ab, q3.y);
                        fma2(acc[8], ab, q4.x);
                        fma2(acc[9], ab, q4.y);
                    }
                    float res1[19];
                    finish_row(acc, res1);
#pragma unroll
                    for (int k = 0; k < 19; ++k)
                        out[(size_t)row * 19 + k] = res1[k];
                }
            }
            __syncwarp();
        }
        p ^= 1;
    }

    // drain outstanding bulk stores before kernel exit
    bulk_wait_all0();
}

extern "C" void kernel_launch(void* const* d_in, const int* in_sizes, int n_in,
                              void* d_out, int out_size) {
    const float* p1 = (const float*)d_in[0];
    const float* p2 = (const float*)d_in[1];
    const float* W1 = (const float*)d_in[2];
    const float* W2 = (const float*)d_in[3];
    float* out = (float*)d_out;

    int B = in_sizes[0] / 10;
    int ntiles = (B + TILE - 1) / TILE;   // B=262144 -> 1024 tiles

    // one wave at occupancy 5 (128-thread CTAs) on 148 SMs
    int G = 148 * 5;
    if (G > ntiles) G = ntiles;
    if (G < 1) G = 1;

    bacon_kernel<<<G, CTA>>>(p1, p2, W1, W2, out, B, ntiles);
}